// round 5
// baseline (speedup 1.0000x reference)
#include <cuda_runtime.h>
#include <cstdint>

// NN_16_1_Pooling: x[16,64,224,224] f32 -> per 2x2 patch MLP (4->16 relu ->1)
// -> out[16,64,112,112] f32.
//
// R5: register ping-pong capped in-flight bytes at ~24KB/SM (DRAM stuck 58%).
// Now cp.async.cg stages input into SMEM (3-stage ring, commit per stage,
// wait_group 2): two full stages (48KB/SM) are continuously outstanding,
// independent of register count. Layout [stage][r][tid] makes both the async
// stores and LDS.128 read-backs conflict-free, and each thread touches only
// its own slots -> zero block-level synchronization.

typedef unsigned long long u64;

#define W4 56                        // input row pitch in float4
#define IN_STEP (18 * 224 * 56)      // 18 planes, in float4 units
#define OUT_STEP (18 * 112 * 56)     // 18 planes, in float2 units
#define OUT_PITCH2 56                // output row pitch in float2

__device__ __forceinline__ u64 pk2(float lo, float hi) {
    u64 r;
    asm("mov.b64 %0, {%1, %2};" : "=l"(r) : "f"(lo), "f"(hi));
    return r;
}
__device__ __forceinline__ u64 fma2(u64 a, u64 b, u64 c) {
    u64 d;
    asm("fma.rn.f32x2 %0, %1, %2, %3;" : "=l"(d) : "l"(a), "l"(b), "l"(c));
    return d;
}
__device__ __forceinline__ float2 upk(u64 v) {
    float lo, hi;
    asm("mov.b64 {%0, %1}, %2;" : "=f"(lo), "=f"(hi) : "l"(v));
    return make_float2(lo, hi);
}

__device__ __forceinline__ void cp16(uint32_t saddr, const float4* g) {
    asm volatile("cp.async.cg.shared.global [%0], [%1], 16;"
                 :: "r"(saddr), "l"(g));
}
#define CP_COMMIT() asm volatile("cp.async.commit_group;" ::: "memory")
#define CP_WAIT2()  asm volatile("cp.async.wait_group 2;" ::: "memory")

struct Wts {
    u64 w1p[8][4];
    u64 b1p[8];
    u64 w2p[8];
    float bias2;
};

// issue one stage: 4 x 16B cp.async into [stage][r][tid]
__device__ __forceinline__ void issue4(uint32_t stage_base, const float4* ip) {
    cp16(stage_base,            ip);
    cp16(stage_base + 2048,     ip + W4);
    cp16(stage_base + 2 * 2048, ip + 2 * W4);
    cp16(stage_base + 3 * 2048, ip + 3 * W4);
}

__device__ __forceinline__ void compute_store(const float4* v, const Wts& w,
                                              float2* __restrict__ op) {
    #pragma unroll
    for (int rp = 0; rp < 2; rp++) {
        const float4 tt = v[2 * rp];
        const float4 uu = v[2 * rp + 1];
        float o2[2];
        #pragma unroll
        for (int pa = 0; pa < 2; pa++) {
            const float k0 = pa ? tt.z : tt.x;
            const float k1 = pa ? tt.w : tt.y;
            const float k2 = pa ? uu.z : uu.x;
            const float k3 = pa ? uu.w : uu.y;
            const u64 x0 = pk2(k0, k0);
            const u64 x1 = pk2(k1, k1);
            const u64 x2 = pk2(k2, k2);
            const u64 x3 = pk2(k3, k3);

            u64 accp = pk2(w.bias2, 0.0f);
            #pragma unroll
            for (int hp = 0; hp < 8; hp++) {
                u64 h2 = w.b1p[hp];
                h2 = fma2(w.w1p[hp][0], x0, h2);
                h2 = fma2(w.w1p[hp][1], x1, h2);
                h2 = fma2(w.w1p[hp][2], x2, h2);
                h2 = fma2(w.w1p[hp][3], x3, h2);
                const float2 hv = upk(h2);
                const u64 rl = pk2(fmaxf(hv.x, 0.0f), fmaxf(hv.y, 0.0f));
                accp = fma2(w.w2p[hp], rl, accp);
            }
            const float2 a = upk(accp);
            o2[pa] = a.x + a.y;
        }
        op[rp * OUT_PITCH2] = make_float2(o2[0], o2[1]);
    }
}

__global__ __launch_bounds__(128, 3)
void mlp_pool_kernel(const float* __restrict__ x,
                     const float* __restrict__ W1,
                     const float* __restrict__ b1,
                     const float* __restrict__ W2,
                     const float* __restrict__ b2,
                     float* __restrict__ out)
{
    __shared__ float4 buf[3][4][128];   // [stage][row][tid], 24KB

    Wts w;
    #pragma unroll
    for (int hp = 0; hp < 8; hp++) {
        #pragma unroll
        for (int k = 0; k < 4; k++)
            w.w1p[hp][k] = pk2(__ldg(W1 + (2 * hp) * 4 + k),
                               __ldg(W1 + (2 * hp + 1) * 4 + k));
        w.b1p[hp] = pk2(__ldg(b1 + 2 * hp), __ldg(b1 + 2 * hp + 1));
        w.w2p[hp] = pk2(__ldg(W2 + 2 * hp), __ldg(W2 + 2 * hp + 1));
    }
    w.bias2 = __ldg(b2);

    const int tid = blockIdx.x * blockDim.x + threadIdx.x;   // < 56448
    const int j = tid % 56;
    const int t = tid / 56;
    const int q = t % 56;
    const int chan0 = t / 56;                 // 0..17
    const int n = (1023 - chan0) / 18 + 1;    // 56 or 57

    const float4* ip = (const float4*)x
                     + (long long)chan0 * (224 * 56) + (4 * q) * W4 + j;
    float2* op = (float2*)out
               + (long long)chan0 * (112 * 56) + (2 * q) * OUT_PITCH2 + j;

    const uint32_t s0 = (uint32_t)__cvta_generic_to_shared(&buf[0][0][threadIdx.x]);
    const uint32_t s1 = s0 + 8192;
    const uint32_t s2 = s0 + 16384;

    // Prologue: stages 0,1 (n >= 56, always valid).
    issue4(s0, ip); CP_COMMIT(); ip += IN_STEP;
    issue4(s1, ip); CP_COMMIT(); ip += IN_STEP;

    float4 v[4];
    int i = 0;
    for (;;) {
        // iter i: compute buf[i%3], prefetch stage i+2 into buf[(i+2)%3]
        if (i + 2 < n) issue4(s2, ip);
        CP_COMMIT(); CP_WAIT2(); ip += IN_STEP;
        #pragma unroll
        for (int r = 0; r < 4; r++) v[r] = buf[0][r][threadIdx.x];
        compute_store(v, w, op); op += OUT_STEP;
        if (++i >= n) break;

        if (i + 2 < n) issue4(s0, ip);
        CP_COMMIT(); CP_WAIT2(); ip += IN_STEP;
        #pragma unroll
        for (int r = 0; r < 4; r++) v[r] = buf[1][r][threadIdx.x];
        compute_store(v, w, op); op += OUT_STEP;
        if (++i >= n) break;

        if (i + 2 < n) issue4(s1, ip);
        CP_COMMIT(); CP_WAIT2(); ip += IN_STEP;
        #pragma unroll
        for (int r = 0; r < 4; r++) v[r] = buf[2][r][threadIdx.x];
        compute_store(v, w, op); op += OUT_STEP;
        if (++i >= n) break;
    }
}

extern "C" void kernel_launch(void* const* d_in, const int* in_sizes, int n_in,
                              void* d_out, int out_size)
{
    const float* x  = (const float*)d_in[0];
    const float* W1 = (const float*)d_in[1];
    const float* b1 = (const float*)d_in[2];
    const float* W2 = (const float*)d_in[3];
    const float* b2 = (const float*)d_in[4];
    float* out = (float*)d_out;

    // 441 blocks x 128 threads = 56448 threads = 56(j) * 56(q) * 18(chan0).
    mlp_pool_kernel<<<441, 128>>>(x, W1, b1, W2, b2, out);
}

// round 6
// speedup vs baseline: 1.2725x; 1.2725x over previous
#include <cuda_runtime.h>
#include <cstdint>

// NN_16_1_Pooling: x[16,64,224,224] f32 -> per 2x2 patch MLP (4->16 relu ->1)
// -> out[16,64,112,112] f32.
//
// R6: occupancy experiment. R4 (12 warps/SM, 156 regs) sat at 52us with
// fma=50%, DRAM=58%. Either FFMA2 is rt4 (RF wall -> at roofline) or we are
// latency-bound (more warps fix it). This kernel drops to ~120 regs
// (w2 weights via volatile smem-broadcast LDS in the epilogue tail, 2
// patches/iter, 3-deep register prefetch ring) -> 4 CTAs/SM = 16 warps.

typedef unsigned long long u64;

#define W4 56                         // input row pitch in float4
#define NPLANE4 (224 * 56)            // float4 per input plane
#define OPLANE2 (112 * 56)            // float2 per output plane
#define CH_STEP 12
#define IN_STEP (CH_STEP * NPLANE4)
#define OUT_STEP (CH_STEP * OPLANE2)

__device__ __forceinline__ u64 pk2(float lo, float hi) {
    u64 r;
    asm("mov.b64 %0, {%1, %2};" : "=l"(r) : "f"(lo), "f"(hi));
    return r;
}
__device__ __forceinline__ u64 fma2(u64 a, u64 b, u64 c) {
    u64 d;
    asm("fma.rn.f32x2 %0, %1, %2, %3;" : "=l"(d) : "l"(a), "l"(b), "l"(c));
    return d;
}
__device__ __forceinline__ float2 upk(u64 v) {
    float lo, hi;
    asm("mov.b64 {%0, %1}, %2;" : "=f"(lo), "=f"(hi) : "l"(v));
    return make_float2(lo, hi);
}
__device__ __forceinline__ u64 lds64(uint32_t a) {
    u64 v;
    asm volatile("ld.shared.b64 %0, [%1];" : "=l"(v) : "r"(a));
    return v;
}

struct Wts {
    u64 w1p[8][4];   // {W1[2hp][k], W1[2hp+1][k]}  -- 64 regs
    u64 b1p[8];      // 16 regs
};

__device__ __forceinline__ void load2(float4* v, const float4* __restrict__ p) {
    v[0] = __ldg(p);
    v[1] = __ldg(p + W4);
}

// one row-pair = 2 patches -> one float2 store
__device__ __forceinline__ void compute2(const float4* v, const Wts& w,
                                         uint32_t w2a, float bias2,
                                         float2* __restrict__ op) {
    const float4 tt = v[0];
    const float4 uu = v[1];
    float o2[2];
    #pragma unroll
    for (int pa = 0; pa < 2; pa++) {
        const float k0 = pa ? tt.z : tt.x;
        const float k1 = pa ? tt.w : tt.y;
        const float k2 = pa ? uu.z : uu.x;
        const float k3 = pa ? uu.w : uu.y;
        const u64 x0 = pk2(k0, k0);
        const u64 x1 = pk2(k1, k1);
        const u64 x2 = pk2(k2, k2);
        const u64 x3 = pk2(k3, k3);

        u64 accp = pk2(bias2, 0.0f);
        #pragma unroll
        for (int hp = 0; hp < 8; hp++) {
            u64 h2 = w.b1p[hp];
            h2 = fma2(w.w1p[hp][0], x0, h2);
            h2 = fma2(w.w1p[hp][1], x1, h2);
            h2 = fma2(w.w1p[hp][2], x2, h2);
            h2 = fma2(w.w1p[hp][3], x3, h2);
            const float2 hv = upk(h2);
            const u64 rl = pk2(fmaxf(hv.x, 0.0f), fmaxf(hv.y, 0.0f));
            accp = fma2(lds64(w2a + hp * 8), rl, accp);
        }
        const float2 a = upk(accp);
        o2[pa] = a.x + a.y;
    }
    *op = make_float2(o2[0], o2[1]);
}

__global__ __launch_bounds__(128, 4)
void mlp_pool_kernel(const float* __restrict__ x,
                     const float* __restrict__ W1,
                     const float* __restrict__ b1,
                     const float* __restrict__ W2,
                     const float* __restrict__ b2,
                     float* __restrict__ out)
{
    __shared__ u64 s_w2[8];
    __shared__ float s_b2;
    if (threadIdx.x < 8) {
        s_w2[threadIdx.x] = pk2(__ldg(W2 + 2 * threadIdx.x),
                                __ldg(W2 + 2 * threadIdx.x + 1));
        if (threadIdx.x == 0) s_b2 = __ldg(b2);
    }

    Wts w;
    #pragma unroll
    for (int hp = 0; hp < 8; hp++) {
        #pragma unroll
        for (int k = 0; k < 4; k++)
            w.w1p[hp][k] = pk2(__ldg(W1 + (2 * hp) * 4 + k),
                               __ldg(W1 + (2 * hp + 1) * 4 + k));
        w.b1p[hp] = pk2(__ldg(b1 + 2 * hp), __ldg(b1 + 2 * hp + 1));
    }
    __syncthreads();
    const float bias2 = s_b2;
    const uint32_t w2a = (uint32_t)__cvta_generic_to_shared(s_w2);

    // 75264 threads = 56(j) x 112(i) x 12(chan0); loop walks chan += 12.
    const int tid = blockIdx.x * blockDim.x + threadIdx.x;
    const int j = tid % 56;
    const int t = tid / 56;
    const int i = t % 112;                 // output row
    const int c0 = t / 112;                // 0..11
    const int n = (1023 - c0) / CH_STEP + 1;   // 85 or 86

    const float4* ip = (const float4*)x + c0 * NPLANE4 + (2 * i) * W4 + j;
    float2* op = (float2*)out + c0 * OPLANE2 + i * 56 + j;

    float4 va[2], vb[2], vc[2];

    // Prologue: 2 stages in flight (n >= 85).
    load2(va, ip); ip += IN_STEP;
    load2(vb, ip); ip += IN_STEP;

    int k = 0;
    for (;;) {
        if (k + 2 < n) { load2(vc, ip); ip += IN_STEP; }
        compute2(va, w, w2a, bias2, op); op += OUT_STEP;
        if (++k >= n) break;

        if (k + 2 < n) { load2(va, ip); ip += IN_STEP; }
        compute2(vb, w, w2a, bias2, op); op += OUT_STEP;
        if (++k >= n) break;

        if (k + 2 < n) { load2(vb, ip); ip += IN_STEP; }
        compute2(vc, w, w2a, bias2, op); op += OUT_STEP;
        if (++k >= n) break;
    }
}

extern "C" void kernel_launch(void* const* d_in, const int* in_sizes, int n_in,
                              void* d_out, int out_size)
{
    const float* x  = (const float*)d_in[0];
    const float* W1 = (const float*)d_in[1];
    const float* b1 = (const float*)d_in[2];
    const float* W2 = (const float*)d_in[3];
    const float* b2 = (const float*)d_in[4];
    float* out = (float*)d_out;

    // 588 blocks x 128 threads = 75264 = 56 * 112 * 12; 4 CTAs/SM on 144 SMs.
    mlp_pool_kernel<<<588, 128>>>(x, W1, b1, W2, b2, out);
}

// round 7
// speedup vs baseline: 1.4742x; 1.1585x over previous
#include <cuda_runtime.h>
#include <cstdint>

// NN_16_1_Pooling: x[16,64,224,224] f32 -> per 2x2 patch MLP (4->16 relu ->1)
// -> out[16,64,112,112] f32.
//
// R7: in-flight-bytes is the controlling variable (16KB->3.0, 24->3.8,
// 32->4.2, 48->4.6 TB/s across rounds). This is R4 with pipeline depth 3->4:
// 3 stages (72KB/SM) continuously pending. The 4th register buffer is paid
// for by moving w2/b2 to smem broadcast (epilogue-tail LDS, latency-tolerant),
// keeping 3 CTAs/SM at the 170-reg cap.

typedef unsigned long long u64;

#define W4 56                        // input row pitch in float4
#define IN_STEP (18 * 224 * 56)      // 18 planes, float4 units
#define OUT_STEP (18 * 112 * 56)     // 18 planes, float2 units
#define OUT_PITCH2 56                // output row pitch in float2

__device__ __forceinline__ u64 pk2(float lo, float hi) {
    u64 r;
    asm("mov.b64 %0, {%1, %2};" : "=l"(r) : "f"(lo), "f"(hi));
    return r;
}
__device__ __forceinline__ u64 fma2(u64 a, u64 b, u64 c) {
    u64 d;
    asm("fma.rn.f32x2 %0, %1, %2, %3;" : "=l"(d) : "l"(a), "l"(b), "l"(c));
    return d;
}
__device__ __forceinline__ float2 upk(u64 v) {
    float lo, hi;
    asm("mov.b64 {%0, %1}, %2;" : "=f"(lo), "=f"(hi) : "l"(v));
    return make_float2(lo, hi);
}
__device__ __forceinline__ u64 lds64(uint32_t a) {
    u64 v;
    asm volatile("ld.shared.b64 %0, [%1];" : "=l"(v) : "r"(a));
    return v;
}

struct Wts {
    u64 w1p[8][4];   // {W1[2hp][k], W1[2hp+1][k]} -- 64 regs
    u64 b1p[8];      // 16 regs
};

__device__ __forceinline__ void load4(float4* v, const float4* __restrict__ p) {
    v[0] = __ldg(p);
    v[1] = __ldg(p + W4);
    v[2] = __ldg(p + 2 * W4);
    v[3] = __ldg(p + 3 * W4);
}

__device__ __forceinline__ void compute_store(const float4* v, const Wts& w,
                                              uint32_t w2a, float bias2,
                                              float2* __restrict__ op) {
    #pragma unroll
    for (int rp = 0; rp < 2; rp++) {
        const float4 tt = v[2 * rp];
        const float4 uu = v[2 * rp + 1];
        float o2[2];
        #pragma unroll
        for (int pa = 0; pa < 2; pa++) {
            const float k0 = pa ? tt.z : tt.x;
            const float k1 = pa ? tt.w : tt.y;
            const float k2 = pa ? uu.z : uu.x;
            const float k3 = pa ? uu.w : uu.y;
            const u64 x0 = pk2(k0, k0);
            const u64 x1 = pk2(k1, k1);
            const u64 x2 = pk2(k2, k2);
            const u64 x3 = pk2(k3, k3);

            u64 accp = pk2(bias2, 0.0f);
            #pragma unroll
            for (int hp = 0; hp < 8; hp++) {
                u64 h2 = w.b1p[hp];
                h2 = fma2(w.w1p[hp][0], x0, h2);
                h2 = fma2(w.w1p[hp][1], x1, h2);
                h2 = fma2(w.w1p[hp][2], x2, h2);
                h2 = fma2(w.w1p[hp][3], x3, h2);
                const float2 hv = upk(h2);
                const u64 rl = pk2(fmaxf(hv.x, 0.0f), fmaxf(hv.y, 0.0f));
                accp = fma2(lds64(w2a + hp * 8), rl, accp);
            }
            const float2 a = upk(accp);
            o2[pa] = a.x + a.y;
        }
        op[rp * OUT_PITCH2] = make_float2(o2[0], o2[1]);
    }
}

__global__ __launch_bounds__(128, 3)
void mlp_pool_kernel(const float* __restrict__ x,
                     const float* __restrict__ W1,
                     const float* __restrict__ b1,
                     const float* __restrict__ W2,
                     const float* __restrict__ b2,
                     float* __restrict__ out)
{
    __shared__ u64 s_w2[8];
    __shared__ float s_b2;
    if (threadIdx.x < 8) {
        s_w2[threadIdx.x] = pk2(__ldg(W2 + 2 * threadIdx.x),
                                __ldg(W2 + 2 * threadIdx.x + 1));
        if (threadIdx.x == 0) s_b2 = __ldg(b2);
    }

    Wts w;
    #pragma unroll
    for (int hp = 0; hp < 8; hp++) {
        #pragma unroll
        for (int k = 0; k < 4; k++)
            w.w1p[hp][k] = pk2(__ldg(W1 + (2 * hp) * 4 + k),
                               __ldg(W1 + (2 * hp + 1) * 4 + k));
        w.b1p[hp] = pk2(__ldg(b1 + 2 * hp), __ldg(b1 + 2 * hp + 1));
    }
    __syncthreads();
    const float bias2 = s_b2;
    const uint32_t w2a = (uint32_t)__cvta_generic_to_shared(s_w2);

    // 56448 threads = 56(j) x 56(q) x 18(chan0); j,q fixed, chan += 18.
    const int tid = blockIdx.x * blockDim.x + threadIdx.x;
    const int j = tid % 56;
    const int t = tid / 56;
    const int q = t % 56;                  // output double-row
    const int chan0 = t / 56;              // 0..17
    const int n = (1023 - chan0) / 18 + 1; // 56 or 57

    const float4* ip = (const float4*)x + chan0 * (224 * 56) + (4 * q) * W4 + j;
    float2* op = (float2*)out + chan0 * (112 * 56) + (2 * q) * OUT_PITCH2 + j;

    float4 va[4], vb[4], vc[4], vd[4];

    // Prologue: 3 stages in flight (n >= 56).
    load4(va, ip); ip += IN_STEP;
    load4(vb, ip); ip += IN_STEP;
    load4(vc, ip); ip += IN_STEP;

    int i = 0;
    for (;;) {
        // compute stage i, prefetch stage i+3
        if (i + 3 < n) { load4(vd, ip); ip += IN_STEP; }
        compute_store(va, w, w2a, bias2, op); op += OUT_STEP;
        if (++i >= n) break;

        if (i + 3 < n) { load4(va, ip); ip += IN_STEP; }
        compute_store(vb, w, w2a, bias2, op); op += OUT_STEP;
        if (++i >= n) break;

        if (i + 3 < n) { load4(vb, ip); ip += IN_STEP; }
        compute_store(vc, w, w2a, bias2, op); op += OUT_STEP;
        if (++i >= n) break;

        if (i + 3 < n) { load4(vc, ip); ip += IN_STEP; }
        compute_store(vd, w, w2a, bias2, op); op += OUT_STEP;
        if (++i >= n) break;
    }
}

extern "C" void kernel_launch(void* const* d_in, const int* in_sizes, int n_in,
                              void* d_out, int out_size)
{
    const float* x  = (const float*)d_in[0];
    const float* W1 = (const float*)d_in[1];
    const float* b1 = (const float*)d_in[2];
    const float* W2 = (const float*)d_in[3];
    const float* b2 = (const float*)d_in[4];
    float* out = (float*)d_out;

    // 441 blocks x 128 threads = 56448 = 56 * 56 * 18 (exact cover).
    mlp_pool_kernel<<<441, 128>>>(x, W1, b1, W2, b2, out);
}

// round 9
// speedup vs baseline: 1.5198x; 1.0309x over previous
#include <cuda_runtime.h>
#include <cstdint>

// NN_16_1_Pooling: x[16,64,224,224] f32 -> per 2x2 patch MLP (4->16 relu ->1)
// -> out[16,64,112,112] f32.
//
// R9: R7 with ONE change. R7 issued 32 volatile LDS per iteration (w2 weight
// per hp per patch) in strict order at their consumers, exposing ~29cyc smem
// latency 32x/iter -> issue stuck at 48%. Now the 8 w2 pairs are loaded into
// registers ONCE at the top of compute_store (back-to-back LDS, consumed ~40
// instrs later = hidden), and all output FMA2s run register-only.
// (max.f32x2 from R8 does not exist in PTX; relu stays scalar FMNMX.)

typedef unsigned long long u64;

#define W4 56                        // input row pitch in float4
#define IN_STEP (18 * 224 * 56)      // 18 planes, float4 units
#define OUT_STEP (18 * 112 * 56)     // 18 planes, float2 units
#define OUT_PITCH2 56                // output row pitch in float2

__device__ __forceinline__ u64 pk2(float lo, float hi) {
    u64 r;
    asm("mov.b64 %0, {%1, %2};" : "=l"(r) : "f"(lo), "f"(hi));
    return r;
}
__device__ __forceinline__ u64 fma2(u64 a, u64 b, u64 c) {
    u64 d;
    asm("fma.rn.f32x2 %0, %1, %2, %3;" : "=l"(d) : "l"(a), "l"(b), "l"(c));
    return d;
}
__device__ __forceinline__ float2 upk(u64 v) {
    float lo, hi;
    asm("mov.b64 {%0, %1}, %2;" : "=f"(lo), "=f"(hi) : "l"(v));
    return make_float2(lo, hi);
}
__device__ __forceinline__ u64 lds64v(uint32_t a) {
    u64 v;
    asm volatile("ld.shared.b64 %0, [%1];" : "=l"(v) : "r"(a));
    return v;
}

struct Wts {
    u64 w1p[8][4];   // {W1[2hp][k], W1[2hp+1][k]} -- 64 regs
    u64 b1p[8];      // 16 regs
};

__device__ __forceinline__ void load4(float4* v, const float4* __restrict__ p) {
    v[0] = __ldg(p);
    v[1] = __ldg(p + W4);
    v[2] = __ldg(p + 2 * W4);
    v[3] = __ldg(p + 3 * W4);
}

__device__ __forceinline__ void compute_store(const float4* v, const Wts& w,
                                              uint32_t w2a, float bias2,
                                              float2* __restrict__ op) {
    // Hoist w2 pairs into registers ONCE per 4-patch iteration.
    u64 w2r[8];
    #pragma unroll
    for (int hp = 0; hp < 8; hp++) w2r[hp] = lds64v(w2a + hp * 8);

    #pragma unroll
    for (int rp = 0; rp < 2; rp++) {
        const float4 tt = v[2 * rp];
        const float4 uu = v[2 * rp + 1];
        float o2[2];
        #pragma unroll
        for (int pa = 0; pa < 2; pa++) {
            const float k0 = pa ? tt.z : tt.x;
            const float k1 = pa ? tt.w : tt.y;
            const float k2 = pa ? uu.z : uu.x;
            const float k3 = pa ? uu.w : uu.y;
            const u64 x0 = pk2(k0, k0);
            const u64 x1 = pk2(k1, k1);
            const u64 x2 = pk2(k2, k2);
            const u64 x3 = pk2(k3, k3);

            u64 accp = pk2(bias2, 0.0f);
            #pragma unroll
            for (int hp = 0; hp < 8; hp++) {
                u64 h2 = w.b1p[hp];
                h2 = fma2(w.w1p[hp][0], x0, h2);
                h2 = fma2(w.w1p[hp][1], x1, h2);
                h2 = fma2(w.w1p[hp][2], x2, h2);
                h2 = fma2(w.w1p[hp][3], x3, h2);
                const float2 hv = upk(h2);
                const u64 rl = pk2(fmaxf(hv.x, 0.0f), fmaxf(hv.y, 0.0f));
                accp = fma2(w2r[hp], rl, accp);
            }
            const float2 a = upk(accp);
            o2[pa] = a.x + a.y;
        }
        op[rp * OUT_PITCH2] = make_float2(o2[0], o2[1]);
    }
}

__global__ __launch_bounds__(128, 3)
void mlp_pool_kernel(const float* __restrict__ x,
                     const float* __restrict__ W1,
                     const float* __restrict__ b1,
                     const float* __restrict__ W2,
                     const float* __restrict__ b2,
                     float* __restrict__ out)
{
    __shared__ u64 s_w2[8];
    __shared__ float s_b2;
    if (threadIdx.x < 8) {
        s_w2[threadIdx.x] = pk2(__ldg(W2 + 2 * threadIdx.x),
                                __ldg(W2 + 2 * threadIdx.x + 1));
        if (threadIdx.x == 0) s_b2 = __ldg(b2);
    }

    Wts w;
    #pragma unroll
    for (int hp = 0; hp < 8; hp++) {
        #pragma unroll
        for (int k = 0; k < 4; k++)
            w.w1p[hp][k] = pk2(__ldg(W1 + (2 * hp) * 4 + k),
                               __ldg(W1 + (2 * hp + 1) * 4 + k));
        w.b1p[hp] = pk2(__ldg(b1 + 2 * hp), __ldg(b1 + 2 * hp + 1));
    }
    __syncthreads();
    const float bias2 = s_b2;
    const uint32_t w2a = (uint32_t)__cvta_generic_to_shared(s_w2);

    // 56448 threads = 56(j) x 56(q) x 18(chan0); j,q fixed, chan += 18.
    const int tid = blockIdx.x * blockDim.x + threadIdx.x;
    const int j = tid % 56;
    const int t = tid / 56;
    const int q = t % 56;                  // output double-row
    const int chan0 = t / 56;              // 0..17
    const int n = (1023 - chan0) / 18 + 1; // 56 or 57

    const float4* ip = (const float4*)x + chan0 * (224 * 56) + (4 * q) * W4 + j;
    float2* op = (float2*)out + chan0 * (112 * 56) + (2 * q) * OUT_PITCH2 + j;

    float4 va[4], vb[4], vc[4], vd[4];

    // Prologue: 3 stages in flight (n >= 56).
    load4(va, ip); ip += IN_STEP;
    load4(vb, ip); ip += IN_STEP;
    load4(vc, ip); ip += IN_STEP;

    int i = 0;
    for (;;) {
        if (i + 3 < n) { load4(vd, ip); ip += IN_STEP; }
        compute_store(va, w, w2a, bias2, op); op += OUT_STEP;
        if (++i >= n) break;

        if (i + 3 < n) { load4(va, ip); ip += IN_STEP; }
        compute_store(vb, w, w2a, bias2, op); op += OUT_STEP;
        if (++i >= n) break;

        if (i + 3 < n) { load4(vb, ip); ip += IN_STEP; }
        compute_store(vc, w, w2a, bias2, op); op += OUT_STEP;
        if (++i >= n) break;

        if (i + 3 < n) { load4(vc, ip); ip += IN_STEP; }
        compute_store(vd, w, w2a, bias2, op); op += OUT_STEP;
        if (++i >= n) break;
    }
}

extern "C" void kernel_launch(void* const* d_in, const int* in_sizes, int n_in,
                              void* d_out, int out_size)
{
    const float* x  = (const float*)d_in[0];
    const float* W1 = (const float*)d_in[1];
    const float* b1 = (const float*)d_in[2];
    const float* W2 = (const float*)d_in[3];
    const float* b2 = (const float*)d_in[4];
    float* out = (float*)d_out;

    // 441 blocks x 128 threads = 56448 = 56 * 56 * 18 (exact cover).
    mlp_pool_kernel<<<441, 128>>>(x, W1, b1, W2, b2, out);
}

// round 10
// speedup vs baseline: 1.5835x; 1.0419x over previous
#include <cuda_runtime.h>
#include <cstdint>

// NN_16_1_Pooling: x[16,64,224,224] f32 -> per 2x2 patch MLP (4->16 relu ->1)
// -> out[16,64,112,112] f32.
//
// R10: 12 warps/SM was fma-ceiling-locked at 54% efficiency (all 3 warps/SMSP
// simultaneously stalled 46% of cycles); the 80 register-resident weight regs
// blocked a 4th CTA. Now weights STREAM from smem per-hp (3x ld.shared.v2.b64
// broadcast per hp, ~12 transient regs) -> ~117 regs -> 4 CTAs/SM = 16 warps.
// Same fma-bound ceiling, twice the stall coverage. 3-buffer ring of 4xLDG.128
// stages keeps 64KB/SM in flight. Guard-free 39-iter main loop (13 x 3-stage
// blocks), guarded 3-4 iter tail. n in {42,43} with 56x56x24 exact cover.

typedef unsigned long long u64;

#define W4 56                          // input row pitch in float4
#define IN_STEP (24 * 224 * 56)        // 24 planes, float4 units
#define OUT_STEP (24 * 112 * 56)       // 24 planes, float2 units
#define OUT_PITCH2 56                  // output row pitch in float2

__device__ __forceinline__ u64 pk2(float lo, float hi) {
    u64 r;
    asm("mov.b64 %0, {%1, %2};" : "=l"(r) : "f"(lo), "f"(hi));
    return r;
}
__device__ __forceinline__ u64 fma2(u64 a, u64 b, u64 c) {
    u64 d;
    asm("fma.rn.f32x2 %0, %1, %2, %3;" : "=l"(d) : "l"(a), "l"(b), "l"(c));
    return d;
}
__device__ __forceinline__ float2 upk(u64 v) {
    float lo, hi;
    asm("mov.b64 {%0, %1}, %2;" : "=f"(lo), "=f"(hi) : "l"(v));
    return make_float2(lo, hi);
}
__device__ __forceinline__ void lds128(u64& a, u64& b, uint32_t addr) {
    asm volatile("ld.shared.v2.b64 {%0, %1}, [%2];" : "=l"(a), "=l"(b) : "r"(addr));
}

__device__ __forceinline__ void load4(float4* v, const float4* __restrict__ p) {
    v[0] = __ldg(p);
    v[1] = __ldg(p + W4);
    v[2] = __ldg(p + 2 * W4);
    v[3] = __ldg(p + 3 * W4);
}

// 4 patches (2 row-pairs) per call; weights streamed from smem per hp.
__device__ __forceinline__ void compute_store(const float4* v, uint32_t wa,
                                              float bias2,
                                              float2* __restrict__ op) {
    // Broadcast x packs: x[p][k] = {k_val, k_val}
    u64 xp[4][4];
    #pragma unroll
    for (int rp = 0; rp < 2; rp++) {
        const float4 tt = v[2 * rp];
        const float4 uu = v[2 * rp + 1];
        xp[2 * rp + 0][0] = pk2(tt.x, tt.x);
        xp[2 * rp + 0][1] = pk2(tt.y, tt.y);
        xp[2 * rp + 0][2] = pk2(uu.x, uu.x);
        xp[2 * rp + 0][3] = pk2(uu.y, uu.y);
        xp[2 * rp + 1][0] = pk2(tt.z, tt.z);
        xp[2 * rp + 1][1] = pk2(tt.w, tt.w);
        xp[2 * rp + 1][2] = pk2(uu.z, uu.z);
        xp[2 * rp + 1][3] = pk2(uu.w, uu.w);
    }

    u64 acc[4];
    #pragma unroll
    for (int p = 0; p < 4; p++) acc[p] = pk2(bias2, 0.0f);

    #pragma unroll
    for (int hp = 0; hp < 8; hp++) {
        // 6 u64 weights for this hp: {w1k0,w1k1} {w1k2,w1k3} {b1,w2}
        u64 w0, w1c, w2c, w3c, bp, w2o;
        const uint32_t a = wa + hp * 64;
        lds128(w0, w1c, a);
        lds128(w2c, w3c, a + 16);
        lds128(bp, w2o, a + 32);
        #pragma unroll
        for (int p = 0; p < 4; p++) {
            u64 h2 = fma2(w0, xp[p][0], bp);
            h2 = fma2(w1c, xp[p][1], h2);
            h2 = fma2(w2c, xp[p][2], h2);
            h2 = fma2(w3c, xp[p][3], h2);
            const float2 hv = upk(h2);
            const u64 rl = pk2(fmaxf(hv.x, 0.0f), fmaxf(hv.y, 0.0f));
            acc[p] = fma2(w2o, rl, acc[p]);
        }
    }

    const float2 a0 = upk(acc[0]);
    const float2 a1 = upk(acc[1]);
    const float2 a2 = upk(acc[2]);
    const float2 a3 = upk(acc[3]);
    op[0]          = make_float2(a0.x + a0.y, a1.x + a1.y);
    op[OUT_PITCH2] = make_float2(a2.x + a2.y, a3.x + a3.y);
}

__global__ __launch_bounds__(128, 4)
void mlp_pool_kernel(const float* __restrict__ x,
                     const float* __restrict__ W1,
                     const float* __restrict__ b1,
                     const float* __restrict__ W2,
                     const float* __restrict__ b2,
                     float* __restrict__ out)
{
    // s_wp[hp] = {w1p[k0],w1p[k1],w1p[k2],w1p[k3], b1p, w2p} padded to 64B
    __shared__ u64 s_wp[8][8];
    __shared__ float s_b2;
    if (threadIdx.x < 8) {
        const int hp = threadIdx.x;
        #pragma unroll
        for (int k = 0; k < 4; k++)
            s_wp[hp][k] = pk2(__ldg(W1 + (2 * hp) * 4 + k),
                              __ldg(W1 + (2 * hp + 1) * 4 + k));
        s_wp[hp][4] = pk2(__ldg(b1 + 2 * hp), __ldg(b1 + 2 * hp + 1));
        s_wp[hp][5] = pk2(__ldg(W2 + 2 * hp), __ldg(W2 + 2 * hp + 1));
        if (hp == 0) s_b2 = __ldg(b2);
    }
    __syncthreads();
    const float bias2 = s_b2;
    const uint32_t wa = (uint32_t)__cvta_generic_to_shared(s_wp);

    // 75264 threads = 56(j) x 56(q) x 24(c0); j,q fixed, chan += 24.
    const int tid = blockIdx.x * blockDim.x + threadIdx.x;
    const int j = tid % 56;
    const int t = tid / 56;
    const int q = t % 56;                   // output double-row
    const int c0 = t / 56;                  // 0..23
    const int n = (1023 - c0) / 24 + 1;     // 43 (c0<=15) or 42

    const float4* ip = (const float4*)x + c0 * (224 * 56) + (4 * q) * W4 + j;
    float2* op = (float2*)out + c0 * (112 * 56) + (2 * q) * OUT_PITCH2 + j;

    float4 va[4], vb[4], vc[4];

    // Prologue: stages 0,1.
    load4(va, ip); ip += IN_STEP;
    load4(vb, ip); ip += IN_STEP;

    // Guard-free main: 39 iterations = 13 x 3-stage ring blocks.
    // Iter i prefetches stage i+2 (max 40 <= 41 <= n-1, n >= 42: always valid).
    for (int blk = 0; blk < 13; blk++) {
        load4(vc, ip); ip += IN_STEP;
        compute_store(va, wa, bias2, op); op += OUT_STEP;
        load4(va, ip); ip += IN_STEP;
        compute_store(vb, wa, bias2, op); op += OUT_STEP;
        load4(vb, ip); ip += IN_STEP;
        compute_store(vc, wa, bias2, op); op += OUT_STEP;
    }

    // Tail: va=stage 39, vb=stage 40; ip points at stage 41 (always valid).
    load4(vc, ip); ip += IN_STEP;                       // stage 41
    compute_store(va, wa, bias2, op); op += OUT_STEP;   // 39
    if (n > 42) load4(va, ip);                          // stage 42 (c0<=15)
    compute_store(vb, wa, bias2, op); op += OUT_STEP;   // 40
    compute_store(vc, wa, bias2, op); op += OUT_STEP;   // 41
    if (n > 42) compute_store(va, wa, bias2, op);       // 42
}

extern "C" void kernel_launch(void* const* d_in, const int* in_sizes, int n_in,
                              void* d_out, int out_size)
{
    const float* x  = (const float*)d_in[0];
    const float* W1 = (const float*)d_in[1];
    const float* b1 = (const float*)d_in[2];
    const float* W2 = (const float*)d_in[3];
    const float* b2 = (const float*)d_in[4];
    float* out = (float*)d_out;

    // 588 blocks x 128 threads = 75264 = 56 * 56 * 24; 4 CTAs/SM.
    mlp_pool_kernel<<<588, 128>>>(x, W1, b1, W2, b2, out);
}